// round 16
// baseline (speedup 1.0000x reference)
#include <cuda_runtime.h>
#include <cuda_bf16.h>
#include <stdint.h>

// 12-qubit StronglyEntanglingLayers simulator (QDEPTH=8, WIRES=12, reps=1).
//  - normalize/denormalize cancels (circuit is linear) -> skipped
//  - CNOT layers = GF(2)-linear bit maps, folded into addressing
//  - Rot = RZ(omega) RY(theta) RZ(phi): Dphi fused into g0 load, Domega into
//    g2 store (bit-linear in the layer's own logical basis only).
//  - RY pair-update = rotation by theta/2 via 3-shear lifting
//    (t = tan(theta/4), s = sin(theta/2)): 6 FMA/pair.
//  - init kernel precomputes gate tables, 256-entry nonlocal phasors, and
//    per-thread fused coset chains. Main kernel = FMA + Gray-XOR + LDS only.
//  - __launch_bounds__(256,4): 4 CTAs/SM -> 592 state-slots >= 1024/2, cutting
//    wave quantization from 3 sequential states/SM to 2 (structural ~33%).
//  - coset entry for next group prefetched before the barrier (hides LDG).
//  - conflict-free LDS.64 coset addressing (host greedy selection).
//  - output: out_size == B*4096 -> real-part float32; == 2*B*4096 -> interleaved.

#define NWIRES 12
#define QD 8
#define NSTATE 4096
#define TPB 256

struct GParams {
    unsigned int   C2[QD][3][8];   // bits 0-11 physical, 12-15 flip, 16-27 logical
    unsigned short Mm[QD][3][4];   // gate masks (physical images of group logical bits)
    unsigned short Mf[NWIRES];     // final accumulated map (output addressing)
};

// ---- per-launch precomputed tables (written by init_kernel) ----
__device__ unsigned d_coset[QD * 3][TPB];    // fused coset chain per (l*3+g, t)
__device__ float2   d_qphi[QD][256];         // phi nonlocal phasor (logical bits 0..7)
__device__ float2   d_qom [QD][256];         // omega nonlocal phasor (logical bits 4..11)
__device__ float2   d_TpCg[QD][16];          // phi local phasors (logical bits 8..11)
__device__ float2   d_ToCg[QD][16];          // omega local phasors (logical bits 0..3)
__device__ float    d_sUyg[QD * NWIRES][2];  // RY lifting coeffs (tan(th/4), sin(th/2))

__device__ __forceinline__ float2 cmulf(float2 a, float2 b) {
    return make_float2(a.x * b.x - a.y * b.y, a.x * b.y + a.y * b.x);
}

__global__ void init_kernel(const float* __restrict__ wts, int wN, GParams gp)
{
    __shared__ float aphi[NWIRES], aom[NWIRES];
    const int l = blockIdx.x;
    const int t = threadIdx.x;

    if (t < NWIRES) {
        const int gi = l * NWIRES + t;
        float phi = 0.f, th = 0.f, om = 0.f;
        if (gi * 3 + 2 < wN) {
            phi = tanhf(wts[gi * 3 + 0]);
            th  = tanhf(wts[gi * 3 + 1]);
            om  = tanhf(wts[gi * 3 + 2]);
        }
        // pair rotation angle alpha = th/2; lifting uses tan(alpha/2), sin(alpha)
        d_sUyg[gi][0] = tanf(0.25f * th);
        d_sUyg[gi][1] = sinf(0.5f  * th);
        const int b = NWIRES - 1 - t;   // axis w <-> logical bit 11-w
        aphi[b] = phi;  aom[b] = om;
    }
    __syncthreads();

    float Phi = 0.f, Om = 0.f;
    #pragma unroll
    for (int b = 0; b < NWIRES; b++) { Phi += aphi[b]; Om += aom[b]; }

    if (t < 16) {
        float sp = 0.f, so = 0.f;
        #pragma unroll
        for (int k = 0; k < 4; k++)
            if ((t >> k) & 1) { sp += aphi[8 + k]; so += aom[k]; }
        float s_, c_;
        sincosf(sp, &s_, &c_);  d_TpCg[l][t] = make_float2(c_, s_);
        sincosf(so, &s_, &c_);  d_ToCg[l][t] = make_float2(c_, s_);
    }

    // 256-entry nonlocal phasors (global -1/2 phase constants folded in)
    {
        float ap = -0.5f * Phi, ao = -0.5f * Om;
        #pragma unroll
        for (int k = 0; k < 8; k++)
            if ((t >> k) & 1) { ap += aphi[k]; ao += aom[4 + k]; }
        float s_, c_;
        sincosf(ap, &s_, &c_);  d_qphi[l][t] = make_float2(c_, s_);
        sincosf(ao, &s_, &c_);  d_qom[l][t]  = make_float2(c_, s_);
    }

    // fused coset chains
    #pragma unroll
    for (int g = 0; g < 3; g++) {
        unsigned acc = 0;
        #pragma unroll
        for (int k = 0; k < 8; k++)
            acc ^= (0u - (((unsigned)t >> k) & 1u)) & gp.C2[l][g][k];
        d_coset[l * 3 + g][t] = acc;
    }
}

__global__ __launch_bounds__(TPB, 4) void qsim_kernel(
    const float* __restrict__ x, long long xN,
    float* __restrict__ outraw, long long outFloats, int outMode,
    GParams gp)
{
    __shared__ float2 st[NSTATE];           // 32 KB state
    __shared__ float  sUy[QD * NWIRES][2];  // RY lifting coeffs
    __shared__ float2 TpC[QD][16];          // phi local phasors
    __shared__ float2 ToC[QD][16];          // omega local phasors

    const int t = threadIdx.x;
    const int s = blockIdx.x;

    // ---- copy small tables global -> shared ----
    if (t < QD * NWIRES) { sUy[t][0] = d_sUyg[t][0]; sUy[t][1] = d_sUyg[t][1]; }
    if (t < 128) {
        const int l = t >> 4, f = t & 15;
        TpC[l][f] = d_TpCg[l][f];
        ToC[l][f] = d_ToCg[l][f];
    }

    // ---- load state (imag = 0); normalization skipped (linear circuit) ----
    {
        const long long xbase = (long long)s * NSTATE;
        #pragma unroll
        for (int j = 0; j < 16; j++) {
            int i = j * TPB + t;
            long long gi = xbase + i;
            float v = (gi < xN) ? x[gi] : 0.0f;
            st[i] = make_float2(v, 0.0f);
        }
    }

    // prefetch first coset entry while waiting
    unsigned accNext = d_coset[0][t];
    __syncthreads();

    #pragma unroll 1
    for (int lg = 0; lg < QD * 3; lg++) {
        const int l = lg / 3;
        const int g = lg - 3 * l;

        const unsigned acc  = accNext;
        const unsigned pb   = acc & 0xFFFu;
        const unsigned flip = (acc >> 12) & 15u;
        const unsigned Lb   = acc >> 16;

        const unsigned m0 = gp.Mm[l][g][0], m1 = gp.Mm[l][g][1];
        const unsigned m2 = gp.Mm[l][g][2], m3 = gp.Mm[l][g][3];

        // Gray-code visiting order and per-step XOR mask
        const int GO[16] = {0,1,3,2,6,7,5,4,12,13,15,14,10,11,9,8};

        float2 c[16];
        if (g == 0) {
            // Dphi fused into load: amp *= qphi(nonlocal) * TpC[flip^j]
            const float2 q = d_qphi[l][Lb & 255];
            unsigned adr = pb;
            c[0] = cmulf(cmulf(st[adr], q), TpC[l][flip]);
            #pragma unroll
            for (int n = 1; n < 16; n++) {
                unsigned gb = GO[n] ^ GO[n - 1];
                adr ^= (gb & 1 ? m0 : 0u) | (gb & 2 ? m1 : 0u)
                     | (gb & 4 ? m2 : 0u) | (gb & 8 ? m3 : 0u);
                c[GO[n]] = cmulf(cmulf(st[adr], q), TpC[l][flip ^ GO[n]]);
            }
        } else {
            unsigned adr = pb;
            c[0] = st[adr];
            #pragma unroll
            for (int n = 1; n < 16; n++) {
                unsigned gb = GO[n] ^ GO[n - 1];
                adr ^= (gb & 1 ? m0 : 0u) | (gb & 2 ? m1 : 0u)
                     | (gb & 4 ? m2 : 0u) | (gb & 8 ? m3 : 0u);
                c[GO[n]] = st[adr];
            }
        }

        // prefetch next group's coset entry (hides post-barrier LDG)
        if (lg + 1 < QD * 3) accNext = d_coset[lg + 1][t];

        // ---- 4 RY gates (lifting: a-=t*b; b+=s*a; a-=t*b) ----
        #pragma unroll
        for (int sl = 0; sl < 4; sl++) {
            const int wire = 4 * g + 3 - sl;
            float tt = sUy[l * NWIRES + wire][0];
            float ss = sUy[l * NWIRES + wire][1];
            if (flip & (1u << sl)) { tt = -tt; ss = -ss; }   // RY(-th)
            #pragma unroll
            for (int j = 0; j < 16; j++) {
                if (j & (1 << sl)) continue;
                const int j1 = j | (1 << sl);
                float2 a  = c[j];
                float2 b2 = c[j1];
                a.x  = fmaf(-tt, b2.x, a.x);   a.y  = fmaf(-tt, b2.y, a.y);
                b2.x = fmaf( ss, a.x,  b2.x);  b2.y = fmaf( ss, a.y,  b2.y);
                a.x  = fmaf(-tt, b2.x, a.x);   a.y  = fmaf(-tt, b2.y, a.y);
                c[j]  = a;
                c[j1] = b2;
            }
        }

        if (g == 2) {
            // Domega fused into store
            const float2 q = d_qom[l][(Lb >> 4) & 255];
            unsigned adr = pb;
            st[adr] = cmulf(cmulf(c[0], q), ToC[l][flip]);
            #pragma unroll
            for (int n = 1; n < 16; n++) {
                unsigned gb = GO[n] ^ GO[n - 1];
                adr ^= (gb & 1 ? m0 : 0u) | (gb & 2 ? m1 : 0u)
                     | (gb & 4 ? m2 : 0u) | (gb & 8 ? m3 : 0u);
                st[adr] = cmulf(cmulf(c[GO[n]], q), ToC[l][flip ^ GO[n]]);
            }
        } else {
            unsigned adr = pb;
            st[adr] = c[0];
            #pragma unroll
            for (int n = 1; n < 16; n++) {
                unsigned gb = GO[n] ^ GO[n - 1];
                adr ^= (gb & 1 ? m0 : 0u) | (gb & 2 ? m1 : 0u)
                     | (gb & 4 ? m2 : 0u) | (gb & 8 ? m3 : 0u);
                st[adr] = c[GO[n]];
            }
        }
        __syncthreads();
    }

    // ---- output: logical index j*256+t lives at physical Mf(index) ----
    unsigned Mt = 0;
    #pragma unroll
    for (int k = 0; k < 8; k++)
        Mt ^= (0u - (((unsigned)t >> k) & 1u)) & (unsigned)gp.Mf[k];

    const long long obase = (long long)s * NSTATE;
    #pragma unroll
    for (int j = 0; j < 16; j++) {
        unsigned a2 = Mt ^ ((j & 1) ? gp.Mf[8]  : 0u) ^ ((j & 2) ? gp.Mf[9]  : 0u)
                         ^ ((j & 4) ? gp.Mf[10] : 0u) ^ ((j & 8) ? gp.Mf[11] : 0u);
        long long amp = obase + j * TPB + t;
        float2 v = st[a2];
        if (outMode == 0) {
            if (amp < outFloats) outraw[amp] = v.x;
        } else {
            long long f0 = 2 * amp;
            if (f0 + 1 < outFloats) {
                outraw[f0]     = v.x;
                outraw[f0 + 1] = v.y;
            }
        }
    }
}

// ---------------- host ----------------

static inline unsigned short xor_map(const unsigned short* cols, unsigned v) {
    unsigned acc = 0;
    for (int k = 0; k < NWIRES; k++)
        if ((v >> k) & 1u) acc ^= cols[k];
    return (unsigned short)acc;
}

extern "C" void kernel_launch(void* const* d_in, const int* in_sizes, int n_in,
                              void* d_out, int out_size)
{
    const float* x   = nullptr;
    const float* wts = nullptr;
    long long xN = 0; int wN = 0, batch = 0;
    for (int i = 0; i < n_in; i++) {
        const int sz = in_sizes[i];
        if (sz == QD * NWIRES * 3) {
            wts = (const float*)d_in[i];  wN = sz;
        } else if (sz >= NSTATE && (sz % NSTATE) == 0) {
            x = (const float*)d_in[i];  xN = sz;  batch = sz / NSTATE;
        }
    }
    if (!x || !wts || batch <= 0) return;

    const long long nAmp = (long long)batch * NSTATE;
    int outMode = (out_size == 2LL * nAmp) ? 1 : 0;
    long long outFloats = (long long)out_size;

    // ---- accumulated GF(2) maps per layer ----
    unsigned short Ml[QD + 1][NWIRES];
    {
        unsigned short M[NWIRES];
        for (int b = 0; b < NWIRES; b++) M[b] = (unsigned short)(1u << b);
        for (int l = 0; l < QD; l++) {
            for (int b = 0; b < NWIRES; b++) Ml[l][b] = M[b];
            const int r = (l % (NWIRES - 1)) + 1;
            unsigned short Mn[NWIRES];
            for (int b = 0; b < NWIRES; b++) {
                unsigned i = 1u << b;
                for (int w = NWIRES - 1; w >= 0; w--) {
                    const int bc = NWIRES - 1 - w;
                    const int bt = NWIRES - 1 - ((w + r) % NWIRES);
                    i ^= ((i >> bc) & 1u) << bt;
                }
                Mn[b] = xor_map(M, i);
            }
            for (int b = 0; b < NWIRES; b++) M[b] = Mn[b];
        }
        for (int b = 0; b < NWIRES; b++) Ml[QD][b] = M[b];
    }

    GParams gp;
    for (int b = 0; b < NWIRES; b++) gp.Mf[b] = Ml[QD][b];

    for (int l = 0; l < QD; l++) {
        // inverse of M_l via [A|I] row reduction
        unsigned rows[NWIRES];
        for (int i = 0; i < NWIRES; i++) {
            unsigned rr = 0;
            for (int j = 0; j < NWIRES; j++)
                rr |= ((Ml[l][j] >> i) & 1u) << j;
            rows[i] = rr | (1u << (12 + i));
        }
        for (int col = 0; col < NWIRES; col++) {
            int piv = -1;
            for (int i = col; i < NWIRES; i++)
                if ((rows[i] >> col) & 1u) { piv = i; break; }
            unsigned tmp = rows[col]; rows[col] = rows[piv]; rows[piv] = tmp;
            for (int i = 0; i < NWIRES; i++)
                if (i != col && ((rows[i] >> col) & 1u)) rows[i] ^= rows[col];
        }
        unsigned short Minv[NWIRES];
        for (int b = 0; b < NWIRES; b++) {
            unsigned v = 0;
            for (int i = 0; i < NWIRES; i++)
                v |= ((rows[i] >> (12 + b)) & 1u) << i;
            Minv[b] = (unsigned short)v;
        }

        for (int g = 0; g < 3; g++) {
            const int lb = 8 - 4 * g;
            unsigned short m4[4];
            for (int sl = 0; sl < 4; sl++) {
                m4[sl] = Ml[l][lb + sl];
                gp.Mm[l][g][sl] = m4[sl];
            }

            unsigned led[NWIRES]; for (int i = 0; i < NWIRES; i++) led[i] = 0;
            auto tryAdd12 = [&](unsigned v, unsigned* L) -> bool {
                while (v) {
                    int b = 31 - __builtin_clz(v);
                    if (!L[b]) { L[b] = v; return true; }
                    v ^= L[b];
                }
                return false;
            };
            for (int sl = 0; sl < 4; sl++) tryAdd12(m4[sl], led);

            unsigned led4[4] = {0, 0, 0, 0};
            auto tryAdd4 = [&](unsigned v, unsigned* L) -> bool {
                v &= 15u;
                while (v) {
                    int b = 31 - __builtin_clz(v);
                    if (!L[b]) { L[b] = v; return true; }
                    v ^= L[b];
                }
                return false;
            };

            int dlist[8], nd = 0;
            for (int b = 0; b < NWIRES; b++)
                if (b < lb || b > lb + 3) dlist[nd++] = b;

            for (int k = 0; k < 8; k++) {
                unsigned chosen = 0; int found = 0;
                for (int pass = 0; pass < 2 && !found; pass++) {
                    const int lim = (pass == 0) ? 256 : 4096;
                    for (int u = 1; u < lim && !found; u++) {
                        unsigned cand;
                        if (pass == 0) {
                            cand = 0;
                            for (int i = 0; i < 8; i++)
                                if ((u >> i) & 1) cand ^= Ml[l][dlist[i]];
                        } else {
                            cand = (unsigned)u;
                        }
                        unsigned L12[NWIRES]; for (int i = 0; i < NWIRES; i++) L12[i] = led[i];
                        if (!tryAdd12(cand, L12)) continue;
                        if (k < 4) {
                            unsigned L4[4] = {led4[0], led4[1], led4[2], led4[3]};
                            if (!tryAdd4(cand, L4)) continue;
                            for (int i = 0; i < 4; i++) led4[i] = L4[i];
                        }
                        for (int i = 0; i < NWIRES; i++) led[i] = L12[i];
                        chosen = cand; found = 1;
                    }
                }
                // logical-space generator + flip nibble
                unsigned vlog = 0;
                for (int i = 0; i < NWIRES; i++)
                    if ((chosen >> i) & 1u) vlog ^= Minv[i];
                unsigned f = (vlog >> lb) & 15u;
                gp.C2[l][g][k] = chosen | (f << 12) | ((unsigned)vlog << 16);
            }
        }
    }

    init_kernel<<<QD, TPB>>>(wts, wN, gp);
    qsim_kernel<<<batch, TPB>>>(x, xN, (float*)d_out, outFloats, outMode, gp);
}